// round 1
// baseline (speedup 1.0000x reference)
#include <cuda_runtime.h>
#include <cstdint>

#define N_NODES 100000
#define E_EDGES 1600000
#define CIN 64

// ---------------- scratch (device globals; no allocation allowed) -------------
__device__ int   g_deg[N_NODES];
__device__ int   g_maxdeg;
__device__ float g_scale;
__device__ float g_bufA[(size_t)N_NODES * 64];
__device__ float g_bufB[(size_t)N_NODES * 64];
__device__ float g_bufZ[(size_t)N_NODES * 64];

// ---------------- degree / norm computation ----------------------------------
__global__ void k_zero()
{
    int i = blockIdx.x * blockDim.x + threadIdx.x;
    if (i < N_NODES) g_deg[i] = 0;
    if (i == 0) g_maxdeg = 0;
}

__global__ void k_deg(const int* __restrict__ src)
{
    int e = blockIdx.x * blockDim.x + threadIdx.x;
    if (e < E_EDGES) atomicAdd(&g_deg[src[e]], 1);
}

__global__ void k_max()
{
    int i = blockIdx.x * blockDim.x + threadIdx.x;
    int v = (i < N_NODES) ? g_deg[i] : 0;
    #pragma unroll
    for (int o = 16; o; o >>= 1) v = max(v, __shfl_xor_sync(0xFFFFFFFFu, v, o));
    if ((threadIdx.x & 31) == 0) atomicMax(&g_maxdeg, v);
}

__global__ void k_fin()
{
    g_scale = 1.0f / (float)max(g_maxdeg, 1);
}

// ---------------- fused dual GEMM + norm_loop epilogue ------------------------
// P[i,c] = (h @ W0)[i,c] + b[c] + norm_loop[i] * z[i,c]
// Z[i,c] = -scale * z[i,c]          (pre-scaled for the edge scatter)
// z = h @ W1.  Optional ReLU applied to h on load.
template<int COUT_T, bool RELU>
__global__ __launch_bounds__(256)
void cheb_gemm(const float* __restrict__ H,
               const float* __restrict__ W0,
               const float* __restrict__ W1,
               const float* __restrict__ B,
               float* __restrict__ P,
               float* __restrict__ Z)
{
    __shared__ float sh[64][65];
    __shared__ float sw0[64][64];
    __shared__ float sw1[64][64];

    const int t    = threadIdx.x;
    const int row0 = blockIdx.x * 64;

    // Load weights (zero-pad columns >= COUT_T)
    for (int i = t; i < 64 * 64; i += 256) {
        int k = i >> 6, c = i & 63;
        float a = 0.f, b2 = 0.f;
        if (c < COUT_T) { a = W0[k * COUT_T + c]; b2 = W1[k * COUT_T + c]; }
        sw0[k][c] = a;
        sw1[k][c] = b2;
    }
    // Load H tile (64 rows x 64 cols), optional ReLU
    for (int i = t; i < 64 * 64; i += 256) {
        int r = i >> 6, k = i & 63;
        int gr = row0 + r;
        float v = (gr < N_NODES) ? H[(size_t)gr * CIN + k] : 0.f;
        if (RELU) v = fmaxf(v, 0.f);
        sh[r][k] = v;
    }
    __syncthreads();

    const int tx = t & 15, ty = t >> 4;
    float acc0[4][4] = {};
    float acc1[4][4] = {};

    #pragma unroll 8
    for (int k = 0; k < 64; k++) {
        float hv[4], w0v[4], w1v[4];
        #pragma unroll
        for (int r = 0; r < 4; r++) hv[r] = sh[ty + 16 * r][k];
        #pragma unroll
        for (int c = 0; c < 4; c++) {
            w0v[c] = sw0[k][tx + 16 * c];
            w1v[c] = sw1[k][tx + 16 * c];
        }
        #pragma unroll
        for (int r = 0; r < 4; r++)
            #pragma unroll
            for (int c = 0; c < 4; c++) {
                acc0[r][c] += hv[r] * w0v[c];
                acc1[r][c] += hv[r] * w1v[c];
            }
    }

    const float scale = g_scale;
    #pragma unroll
    for (int r = 0; r < 4; r++) {
        int gr = row0 + ty + 16 * r;
        if (gr >= N_NODES) continue;
        float nl = (float)g_deg[gr] * scale - 1.0f;
        #pragma unroll
        for (int c = 0; c < 4; c++) {
            int gc = tx + 16 * c;
            if (gc < COUT_T) {
                float z = acc1[r][c];
                Z[(size_t)gr * COUT_T + gc] = -scale * z;
                P[(size_t)gr * COUT_T + gc] = acc0[r][c] + B[gc] + nl * z;
            }
        }
    }
}

// ---------------- edge scatter: P[dst] += Z'[src] -----------------------------
// One thread per (edge, 4-channel quad). Z' already holds -scale * (h @ W1).
template<int COUT_T>
__global__ __launch_bounds__(256)
void cheb_scatter(const int* __restrict__ esrc,
                  const int* __restrict__ edst,
                  const float* __restrict__ Z,
                  float* __restrict__ P)
{
    constexpr int QP = COUT_T / 4;
    int idx = blockIdx.x * blockDim.x + threadIdx.x;
    if (idx >= E_EDGES * QP) return;
    int e = idx / QP;
    int q = idx - e * QP;
    int s = __ldg(&esrc[e]);
    int d = __ldg(&edst[e]);
    float4 z = __ldg(reinterpret_cast<const float4*>(Z + (size_t)s * COUT_T) + q);
    float* pp = P + (size_t)d * COUT_T + 4 * q;
    asm volatile("red.global.add.v4.f32 [%0], {%1, %2, %3, %4};"
                 :: "l"(pp), "f"(z.x), "f"(z.y), "f"(z.z), "f"(z.w)
                 : "memory");
}

// ---------------- log_softmax over 40 channels, one warp per node -------------
__global__ void k_logsoftmax(const float* __restrict__ P, float* __restrict__ out)
{
    int warp = (blockIdx.x * blockDim.x + threadIdx.x) >> 5;
    int lane = threadIdx.x & 31;
    if (warp >= N_NODES) return;
    const float* p = P + (size_t)warp * 40;
    float v0 = p[lane];
    float v1 = (lane < 8) ? p[lane + 32] : -3.0e38f;
    float m = fmaxf(v0, v1);
    #pragma unroll
    for (int o = 16; o; o >>= 1) m = fmaxf(m, __shfl_xor_sync(0xFFFFFFFFu, m, o));
    float s = expf(v0 - m) + ((lane < 8) ? expf(v1 - m) : 0.f);
    #pragma unroll
    for (int o = 16; o; o >>= 1) s += __shfl_xor_sync(0xFFFFFFFFu, s, o);
    float ls = m + logf(s);
    out[(size_t)warp * 40 + lane] = v0 - ls;
    if (lane < 8) out[(size_t)warp * 40 + 32 + lane] = v1 - ls;
}

// ---------------- launch ------------------------------------------------------
extern "C" void kernel_launch(void* const* d_in, const int* in_sizes, int n_in,
                              void* d_out, int out_size)
{
    const float* x    = (const float*)d_in[0];
    const int*   ei   = (const int*)d_in[1];
    const int*   esrc = ei;
    const int*   edst = ei + E_EDGES;
    const float* W0_0 = (const float*)d_in[2];
    const float* W1_0 = (const float*)d_in[3];
    const float* b_0  = (const float*)d_in[4];
    const float* W0_1 = (const float*)d_in[5];
    const float* W1_1 = (const float*)d_in[6];
    const float* b_1  = (const float*)d_in[7];
    const float* W0_2 = (const float*)d_in[8];
    const float* W1_2 = (const float*)d_in[9];
    const float* b_2  = (const float*)d_in[10];

    float *bufA, *bufB, *bufZ;
    cudaGetSymbolAddress((void**)&bufA, g_bufA);
    cudaGetSymbolAddress((void**)&bufB, g_bufB);
    cudaGetSymbolAddress((void**)&bufZ, g_bufZ);

    const int NB_N = (N_NODES + 255) / 256;          // 391
    const int NB_E = (E_EDGES + 255) / 256;          // 6250
    const int NB_G = (N_NODES + 63) / 64;            // 1563 gemm blocks
    const int NB_S64 = (E_EDGES * 16 + 255) / 256;   // 100000
    const int NB_S40 = (E_EDGES * 10 + 255) / 256;   // 62500
    const int NB_LS = (N_NODES * 32 + 255) / 256;    // 12500

    k_zero<<<NB_N, 256>>>();
    k_deg<<<NB_E, 256>>>(esrc);
    k_max<<<NB_N, 256>>>();
    k_fin<<<1, 1>>>();

    // Layer 0: x (no relu) -> bufA
    cheb_gemm<64, false><<<NB_G, 256>>>(x, W0_0, W1_0, b_0, bufA, bufZ);
    cheb_scatter<64><<<NB_S64, 256>>>(esrc, edst, bufZ, bufA);

    // Layer 1: relu(bufA) -> bufB
    cheb_gemm<64, true><<<NB_G, 256>>>(bufA, W0_1, W1_1, b_1, bufB, bufZ);
    cheb_scatter<64><<<NB_S64, 256>>>(esrc, edst, bufZ, bufB);

    // Layer 2: relu(bufB) -> bufA (40 channels)
    cheb_gemm<40, true><<<NB_G, 256>>>(bufB, W0_2, W1_2, b_2, bufA, bufZ);
    cheb_scatter<40><<<NB_S40, 256>>>(esrc, edst, bufZ, bufA);

    k_logsoftmax<<<NB_LS, 256>>>(bufA, (float*)d_out);
}

// round 2
// speedup vs baseline: 1.4304x; 1.4304x over previous
#include <cuda_runtime.h>
#include <cuda_fp16.h>
#include <cstdint>

#define N_NODES 100000
#define E_EDGES 1600000
#define SCAN_CHUNK 1024
#define NB_SCAN ((N_NODES + SCAN_CHUNK - 1) / SCAN_CHUNK)   // 98

// ---------------- scratch (device globals; no allocation allowed) -------------
__device__ int    g_deg_src[N_NODES];
__device__ int    g_deg_dst[N_NODES];
__device__ int    g_cursor[N_NODES];
__device__ int    g_row_start[N_NODES + 1];
__device__ int    g_blockSums[NB_SCAN];
__device__ int    g_blockOff[NB_SCAN];
__device__ int    g_csr_src[E_EDGES];
__device__ int    g_maxdeg;
__device__ float  g_scale;
__device__ float  g_bufP[(size_t)N_NODES * 64];   // GEMM output P0
__device__ float  g_bufA[(size_t)N_NODES * 64];   // layer activations
__device__ float  g_bufB[(size_t)N_NODES * 64];
__device__ __half g_bufZh[(size_t)N_NODES * 64];  // fp16 pre-scaled Z for gather

// ---------------- packed fp32x2 helpers ---------------------------------------
__device__ __forceinline__ unsigned long long pack2(float a, float b) {
    unsigned long long r;
    asm("mov.b64 %0, {%1, %2};" : "=l"(r) : "f"(a), "f"(b));
    return r;
}
__device__ __forceinline__ void unpack2(unsigned long long p, float& a, float& b) {
    asm("mov.b64 {%0, %1}, %2;" : "=f"(a), "=f"(b) : "l"(p));
}
__device__ __forceinline__ void ffma2(unsigned long long& d,
                                      unsigned long long a, unsigned long long b) {
    asm("fma.rn.f32x2 %0, %1, %2, %0;" : "+l"(d) : "l"(a), "l"(b));
}

// ---------------- degrees / norm ----------------------------------------------
__global__ void k_init()
{
    int i = blockIdx.x * blockDim.x + threadIdx.x;
    if (i < N_NODES) { g_deg_src[i] = 0; g_deg_dst[i] = 0; }
    if (i == 0) g_maxdeg = 0;
}

__global__ void k_deg(const int* __restrict__ esrc, const int* __restrict__ edst)
{
    int e = blockIdx.x * blockDim.x + threadIdx.x;
    if (e < E_EDGES) {
        atomicAdd(&g_deg_src[esrc[e]], 1);
        atomicAdd(&g_deg_dst[edst[e]], 1);
    }
}

__global__ void k_max()
{
    int i = blockIdx.x * blockDim.x + threadIdx.x;
    int v = (i < N_NODES) ? g_deg_src[i] : 0;
    #pragma unroll
    for (int o = 16; o; o >>= 1) v = max(v, __shfl_xor_sync(0xFFFFFFFFu, v, o));
    if ((threadIdx.x & 31) == 0) atomicMax(&g_maxdeg, v);
}

__global__ void k_fin() { g_scale = 1.0f / (float)max(g_maxdeg, 1); }

// ---------------- exclusive scan of deg_dst -> row_start ----------------------
__global__ __launch_bounds__(256) void k_scan1()
{
    __shared__ int warp_tot[8];
    int b = blockIdx.x, t = threadIdx.x;
    int base = b * SCAN_CHUNK + t * 4;
    int v0 = (base + 0 < N_NODES) ? g_deg_dst[base + 0] : 0;
    int v1 = (base + 1 < N_NODES) ? g_deg_dst[base + 1] : 0;
    int v2 = (base + 2 < N_NODES) ? g_deg_dst[base + 2] : 0;
    int v3 = (base + 3 < N_NODES) ? g_deg_dst[base + 3] : 0;
    int s1 = v0, s2 = s1 + v1, s3 = s2 + v2, tot = s3 + v3;

    int lane = t & 31, w = t >> 5;
    int inc = tot;
    #pragma unroll
    for (int o = 1; o < 32; o <<= 1) {
        int n = __shfl_up_sync(0xFFFFFFFFu, inc, o);
        if (lane >= o) inc += n;
    }
    if (lane == 31) warp_tot[w] = inc;
    __syncthreads();
    if (t == 0) {
        int run = 0;
        #pragma unroll
        for (int i = 0; i < 8; i++) { int x = warp_tot[i]; warp_tot[i] = run; run += x; }
        g_blockSums[b] = run;
    }
    __syncthreads();
    int excl = warp_tot[w] + (inc - tot);
    if (base + 0 < N_NODES) g_row_start[base + 0] = excl;
    if (base + 1 < N_NODES) g_row_start[base + 1] = excl + s1;
    if (base + 2 < N_NODES) g_row_start[base + 2] = excl + s2;
    if (base + 3 < N_NODES) g_row_start[base + 3] = excl + s3;
}

__global__ void k_scan2()
{
    int run = 0;
    for (int b = 0; b < NB_SCAN; b++) { g_blockOff[b] = run; run += g_blockSums[b]; }
}

__global__ void k_scan3()
{
    int i = blockIdx.x * blockDim.x + threadIdx.x;
    if (i < N_NODES) {
        int rs = g_row_start[i] + g_blockOff[i >> 10];
        g_row_start[i] = rs;
        g_cursor[i] = rs;
    }
    if (i == 0) g_row_start[N_NODES] = E_EDGES;
}

__global__ void k_fill(const int* __restrict__ esrc, const int* __restrict__ edst)
{
    int e = blockIdx.x * blockDim.x + threadIdx.x;
    if (e < E_EDGES) {
        int d = edst[e];
        int pos = atomicAdd(&g_cursor[d], 1);
        g_csr_src[pos] = esrc[e];
    }
}

// ---------------- fused dual GEMM (FFMA2) + norm_loop epilogue ----------------
// P0[i,c] = (h@W0)[i,c] + b[c] + norm_loop[i]*z[i,c];  Zh[i,c] = fp16(-scale*z)
template<int COUT, bool RELU>
__global__ __launch_bounds__(256, 2)
void cheb_gemm(const float* __restrict__ H,
               const float* __restrict__ W0,
               const float* __restrict__ W1,
               const float* __restrict__ B,
               float* __restrict__ P0,
               __half* __restrict__ Zh)
{
    __shared__ float sh[64][68];
    __shared__ float sw0[64][64];
    __shared__ float sw1[64][64];

    const int t    = threadIdx.x;
    const int row0 = blockIdx.x * 64;

    for (int i = t; i < 64 * 64; i += 256) {
        int k = i >> 6, c = i & 63;
        float a = 0.f, bb = 0.f;
        if (c < COUT) { a = W0[k * COUT + c]; bb = W1[k * COUT + c]; }
        sw0[k][c] = a;
        sw1[k][c] = bb;
    }
    for (int i = t; i < 1024; i += 256) {
        int r = i >> 4, kc = (i & 15) * 4;
        int gr = row0 + r;
        float4 v = make_float4(0.f, 0.f, 0.f, 0.f);
        if (gr < N_NODES) v = *reinterpret_cast<const float4*>(H + (size_t)gr * 64 + kc);
        if (RELU) {
            v.x = fmaxf(v.x, 0.f); v.y = fmaxf(v.y, 0.f);
            v.z = fmaxf(v.z, 0.f); v.w = fmaxf(v.w, 0.f);
        }
        *reinterpret_cast<float4*>(&sh[r][kc]) = v;
    }
    __syncthreads();

    const int tx = t & 15, ty = t >> 4;
    unsigned long long a0[4][2] = {};
    unsigned long long a1[4][2] = {};

    #pragma unroll 4
    for (int k = 0; k < 64; k++) {
        float4 w0q = *reinterpret_cast<const float4*>(&sw0[k][tx * 4]);
        float4 w1q = *reinterpret_cast<const float4*>(&sw1[k][tx * 4]);
        unsigned long long w0p0 = pack2(w0q.x, w0q.y), w0p1 = pack2(w0q.z, w0q.w);
        unsigned long long w1p0 = pack2(w1q.x, w1q.y), w1p1 = pack2(w1q.z, w1q.w);
        #pragma unroll
        for (int r = 0; r < 4; r++) {
            float h = sh[ty + 16 * r][k];
            unsigned long long hp = pack2(h, h);
            ffma2(a0[r][0], hp, w0p0);
            ffma2(a0[r][1], hp, w0p1);
            ffma2(a1[r][0], hp, w1p0);
            ffma2(a1[r][1], hp, w1p1);
        }
    }

    const float scale = g_scale;
    const int cbase = tx * 4;
    float4 bq = make_float4(0.f, 0.f, 0.f, 0.f);
    if (cbase < COUT) bq = *reinterpret_cast<const float4*>(B + cbase);

    #pragma unroll
    for (int r = 0; r < 4; r++) {
        int gr = row0 + ty + 16 * r;
        if (gr >= N_NODES || cbase >= COUT) continue;
        float nl = (float)g_deg_src[gr] * scale - 1.0f;
        float p0, p1, p2, p3, z0, z1, z2, z3;
        unpack2(a0[r][0], p0, p1); unpack2(a0[r][1], p2, p3);
        unpack2(a1[r][0], z0, z1); unpack2(a1[r][1], z2, z3);
        float4 outq;
        outq.x = p0 + bq.x + nl * z0;
        outq.y = p1 + bq.y + nl * z1;
        outq.z = p2 + bq.z + nl * z2;
        outq.w = p3 + bq.w + nl * z3;
        *reinterpret_cast<float4*>(P0 + (size_t)gr * 64 + cbase) = outq;
        __half2 h0 = __floats2half2_rn(-scale * z0, -scale * z1);
        __half2 h1 = __floats2half2_rn(-scale * z2, -scale * z3);
        uint2 hz = make_uint2(*reinterpret_cast<unsigned*>(&h0),
                              *reinterpret_cast<unsigned*>(&h1));
        *reinterpret_cast<uint2*>(Zh + (size_t)gr * 64 + cbase) = hz;
    }
}

// ---------------- CSR gather: Out[i] = P0[i] + sum_{e in in(i)} Zh[src_e] -----
__global__ __launch_bounds__(256)
void cheb_gather64(const float* __restrict__ P0,
                   const __half* __restrict__ Zh,
                   float* __restrict__ Out)
{
    int warp = (blockIdx.x * blockDim.x + threadIdx.x) >> 5;
    int lane = threadIdx.x & 31;
    if (warp >= N_NODES) return;
    const __half2* Z2 = reinterpret_cast<const __half2*>(Zh);
    int beg = g_row_start[warp], end = g_row_start[warp + 1];
    float2 acc = make_float2(0.f, 0.f);
    int e = beg;
    for (; e + 4 <= end; e += 4) {
        int s0 = __ldg(&g_csr_src[e + 0]);
        int s1 = __ldg(&g_csr_src[e + 1]);
        int s2 = __ldg(&g_csr_src[e + 2]);
        int s3 = __ldg(&g_csr_src[e + 3]);
        float2 f0 = __half22float2(__ldg(Z2 + s0 * 32 + lane));
        float2 f1 = __half22float2(__ldg(Z2 + s1 * 32 + lane));
        float2 f2 = __half22float2(__ldg(Z2 + s2 * 32 + lane));
        float2 f3 = __half22float2(__ldg(Z2 + s3 * 32 + lane));
        acc.x += (f0.x + f1.x) + (f2.x + f3.x);
        acc.y += (f0.y + f1.y) + (f2.y + f3.y);
    }
    for (; e < end; e++) {
        int s = __ldg(&g_csr_src[e]);
        float2 f = __half22float2(__ldg(Z2 + s * 32 + lane));
        acc.x += f.x; acc.y += f.y;
    }
    float2 p = *reinterpret_cast<const float2*>(P0 + (size_t)warp * 64 + 2 * lane);
    p.x += acc.x; p.y += acc.y;
    *reinterpret_cast<float2*>(Out + (size_t)warp * 64 + 2 * lane) = p;
}

// ---------------- layer 2: gather (40 ch) fused with log_softmax --------------
__global__ __launch_bounds__(256)
void cheb_gather40_lsm(const float* __restrict__ P0,
                       const __half* __restrict__ Zh,
                       float* __restrict__ out)
{
    int warp = (blockIdx.x * blockDim.x + threadIdx.x) >> 5;
    int lane = threadIdx.x & 31;
    if (warp >= N_NODES) return;
    const __half2* Z2 = reinterpret_cast<const __half2*>(Zh);
    int beg = g_row_start[warp], end = g_row_start[warp + 1];
    float2 acc = make_float2(0.f, 0.f);
    bool act = lane < 20;
    int e = beg;
    for (; e + 4 <= end; e += 4) {
        int s0 = __ldg(&g_csr_src[e + 0]);
        int s1 = __ldg(&g_csr_src[e + 1]);
        int s2 = __ldg(&g_csr_src[e + 2]);
        int s3 = __ldg(&g_csr_src[e + 3]);
        if (act) {
            float2 f0 = __half22float2(__ldg(Z2 + s0 * 32 + lane));
            float2 f1 = __half22float2(__ldg(Z2 + s1 * 32 + lane));
            float2 f2 = __half22float2(__ldg(Z2 + s2 * 32 + lane));
            float2 f3 = __half22float2(__ldg(Z2 + s3 * 32 + lane));
            acc.x += (f0.x + f1.x) + (f2.x + f3.x);
            acc.y += (f0.y + f1.y) + (f2.y + f3.y);
        }
    }
    for (; e < end; e++) {
        int s = __ldg(&g_csr_src[e]);
        if (act) {
            float2 f = __half22float2(__ldg(Z2 + s * 32 + lane));
            acc.x += f.x; acc.y += f.y;
        }
    }
    float v0 = -3.0e38f, v1 = -3.0e38f;
    if (act) {
        float2 p = *reinterpret_cast<const float2*>(P0 + (size_t)warp * 64 + 2 * lane);
        v0 = p.x + acc.x;
        v1 = p.y + acc.y;
    }
    float m = fmaxf(v0, v1);
    #pragma unroll
    for (int o = 16; o; o >>= 1) m = fmaxf(m, __shfl_xor_sync(0xFFFFFFFFu, m, o));
    float s = act ? (expf(v0 - m) + expf(v1 - m)) : 0.f;
    #pragma unroll
    for (int o = 16; o; o >>= 1) s += __shfl_xor_sync(0xFFFFFFFFu, s, o);
    float ls = m + logf(s);
    if (act) {
        float2 o2 = make_float2(v0 - ls, v1 - ls);
        *reinterpret_cast<float2*>(out + (size_t)warp * 40 + 2 * lane) = o2;
    }
}

// ---------------- launch ------------------------------------------------------
extern "C" void kernel_launch(void* const* d_in, const int* in_sizes, int n_in,
                              void* d_out, int out_size)
{
    const float* x    = (const float*)d_in[0];
    const int*   ei   = (const int*)d_in[1];
    const int*   esrc = ei;
    const int*   edst = ei + E_EDGES;
    const float* W0_0 = (const float*)d_in[2];
    const float* W1_0 = (const float*)d_in[3];
    const float* b_0  = (const float*)d_in[4];
    const float* W0_1 = (const float*)d_in[5];
    const float* W1_1 = (const float*)d_in[6];
    const float* b_1  = (const float*)d_in[7];
    const float* W0_2 = (const float*)d_in[8];
    const float* W1_2 = (const float*)d_in[9];
    const float* b_2  = (const float*)d_in[10];

    float *bufP, *bufA, *bufB;
    __half* bufZh;
    cudaGetSymbolAddress((void**)&bufP,  g_bufP);
    cudaGetSymbolAddress((void**)&bufA,  g_bufA);
    cudaGetSymbolAddress((void**)&bufB,  g_bufB);
    cudaGetSymbolAddress((void**)&bufZh, g_bufZh);

    const int NB_N = (N_NODES + 255) / 256;
    const int NB_E = (E_EDGES + 255) / 256;
    const int NB_G = (N_NODES + 63) / 64;
    const int NB_W = (N_NODES * 32 + 255) / 256;   // warp-per-node kernels

    // norm + CSR build
    k_init<<<NB_N, 256>>>();
    k_deg<<<NB_E, 256>>>(esrc, edst);
    k_max<<<NB_N, 256>>>();
    k_fin<<<1, 1>>>();
    k_scan1<<<NB_SCAN, 256>>>();
    k_scan2<<<1, 1>>>();
    k_scan3<<<NB_N, 256>>>();
    k_fill<<<NB_E, 256>>>(esrc, edst);

    // Layer 0
    cheb_gemm<64, false><<<NB_G, 256>>>(x, W0_0, W1_0, b_0, bufP, bufZh);
    cheb_gather64<<<NB_W, 256>>>(bufP, bufZh, bufA);
    // Layer 1
    cheb_gemm<64, true><<<NB_G, 256>>>(bufA, W0_1, W1_1, b_1, bufP, bufZh);
    cheb_gather64<<<NB_W, 256>>>(bufP, bufZh, bufB);
    // Layer 2 + log_softmax
    cheb_gemm<40, true><<<NB_G, 256>>>(bufB, W0_2, W1_2, b_2, bufP, bufZh);
    cheb_gather40_lsm<<<NB_W, 256>>>(bufP, bufZh, (float*)d_out);
}